// round 3
// baseline (speedup 1.0000x reference)
#include <cuda_runtime.h>
#include <math.h>

// Problem constants
#define B_ 128
#define T_ 512
#define I_ 256
#define H_ 1024
#define O_ 256

// Scratch (device globals: allocation-free per harness rules)
__device__ float g_xp[(size_t)B_ * T_ * H_];   // [B][T][H] input projection (+both biases)
__device__ float g_h[2][B_ * H_];              // double-buffered hidden state

// ---------------------------------------------------------------------------
// Kernel 1: xp[bt][h] = sum_i x[bt][i] * W_ih[h][i] + b_ih[h] + b_hh[h]
// GEMM M=65536 (b*T+t), N=1024, K=256. Tile 64x64x16, 256 threads, 4x4/thread.
// ---------------------------------------------------------------------------
__global__ __launch_bounds__(256) void xp_gemm(
    const float* __restrict__ x, const float* __restrict__ W_ih,
    const float* __restrict__ b_ih, const float* __restrict__ b_hh)
{
    const int BM = 64, BN = 64, BK = 16;
    __shared__ float xs[BK][BM + 1];   // [k][m]
    __shared__ float ws[BK][BN + 1];   // [k][n]

    const int m0 = blockIdx.x * BM;
    const int n0 = blockIdx.y * BN;
    const int tid = threadIdx.x;
    const int tx = tid & 15;        // N sub-tile
    const int ty = tid >> 4;        // M sub-tile

    float acc[4][4];
    #pragma unroll
    for (int i = 0; i < 4; i++)
        #pragma unroll
        for (int j = 0; j < 4; j++) acc[i][j] = 0.f;

    const int lc = tid & (BK - 1);      // k within tile
    const int lr0 = tid >> 4;           // 0..15

    for (int k0 = 0; k0 < I_; k0 += BK) {
        #pragma unroll
        for (int rr = 0; rr < 4; rr++) {
            int r = lr0 + rr * 16;
            xs[lc][r] = x[(size_t)(m0 + r) * I_ + k0 + lc];
            ws[lc][r] = W_ih[(size_t)(n0 + r) * I_ + k0 + lc];
        }
        __syncthreads();
        #pragma unroll
        for (int kk = 0; kk < BK; kk++) {
            float a[4], b[4];
            #pragma unroll
            for (int i = 0; i < 4; i++) a[i] = xs[kk][ty * 4 + i];
            #pragma unroll
            for (int j = 0; j < 4; j++) b[j] = ws[kk][tx * 4 + j];
            #pragma unroll
            for (int i = 0; i < 4; i++)
                #pragma unroll
                for (int j = 0; j < 4; j++) acc[i][j] = fmaf(a[i], b[j], acc[i][j]);
        }
        __syncthreads();
    }

    float bias[4];
    #pragma unroll
    for (int j = 0; j < 4; j++) {
        int n = n0 + tx * 4 + j;
        bias[j] = b_ih[n] + b_hh[n];
    }
    #pragma unroll
    for (int i = 0; i < 4; i++) {
        int m = m0 + ty * 4 + i;
        #pragma unroll
        for (int j = 0; j < 4; j++) {
            int n = n0 + tx * 4 + j;
            g_xp[(size_t)m * H_ + n] = acc[i][j] + bias[j];
        }
    }
}

// ---------------------------------------------------------------------------
// init: g_h[0] = hidden
// ---------------------------------------------------------------------------
__global__ void init_h(const float* __restrict__ hidden)
{
    int idx = blockIdx.x * blockDim.x + threadIdx.x;
    if (idx < B_ * H_) g_h[0][idx] = hidden[idx];
}

// ---------------------------------------------------------------------------
// Kernel 2 (per step): h_new[b][j] = tanh(xp[b][t][j] + sum_k h[b][k]*W_hh[j][k])
// GEMM M=128, N=1024, K=1024. Tile 32x32x32, 256 threads, 2x2/thread.
// grid = (4, 32) = 128 CTAs (single wave).
// ---------------------------------------------------------------------------
__global__ __launch_bounds__(256) void step_gemm(
    const float* __restrict__ W_hh, int t)
{
    const int BM = 32, BN = 32, BK = 32;
    __shared__ float hs[BM][BK + 1];
    __shared__ float ws[BN][BK + 1];

    const float* __restrict__ hsrc = g_h[t & 1];
    float* __restrict__ hdst = g_h[(t + 1) & 1];

    const int m0 = blockIdx.x * BM;     // batch tile
    const int n0 = blockIdx.y * BN;     // output-column tile
    const int tid = threadIdx.x;
    const int tx = tid & 15;
    const int ty = tid >> 4;

    float acc00 = 0.f, acc01 = 0.f, acc10 = 0.f, acc11 = 0.f;

    const int lc = tid & 31;            // k within tile
    const int lr0 = tid >> 5;           // 0..7

    for (int k0 = 0; k0 < H_; k0 += BK) {
        #pragma unroll
        for (int rr = 0; rr < 4; rr++) {
            int r = lr0 + rr * 8;
            hs[r][lc] = hsrc[(size_t)(m0 + r) * H_ + k0 + lc];
            ws[r][lc] = W_hh[(size_t)(n0 + r) * H_ + k0 + lc];
        }
        __syncthreads();
        #pragma unroll
        for (int kk = 0; kk < BK; kk++) {
            float a0 = hs[ty * 2 + 0][kk];
            float a1 = hs[ty * 2 + 1][kk];
            float b0 = ws[tx * 2 + 0][kk];
            float b1 = ws[tx * 2 + 1][kk];
            acc00 = fmaf(a0, b0, acc00);
            acc01 = fmaf(a0, b1, acc01);
            acc10 = fmaf(a1, b0, acc10);
            acc11 = fmaf(a1, b1, acc11);
        }
        __syncthreads();
    }

    const int b0i = m0 + ty * 2;
    const int j0 = n0 + tx * 2;
    // xp index: (b*T + t)*H + j
    {
        size_t base0 = ((size_t)b0i * T_ + t) * H_;
        size_t base1 = ((size_t)(b0i + 1) * T_ + t) * H_;
        hdst[(size_t)b0i * H_ + j0]           = tanhf(acc00 + g_xp[base0 + j0]);
        hdst[(size_t)b0i * H_ + j0 + 1]       = tanhf(acc01 + g_xp[base0 + j0 + 1]);
        hdst[(size_t)(b0i + 1) * H_ + j0]     = tanhf(acc10 + g_xp[base1 + j0]);
        hdst[(size_t)(b0i + 1) * H_ + j0 + 1] = tanhf(acc11 + g_xp[base1 + j0 + 1]);
    }
}

// ---------------------------------------------------------------------------
// Kernel 3: out[b][o] = sum_k h_last[b][k] * W_fc[o][k] + b_fc[o]
// h_last lives in g_h[0] (512 steps -> parity 0). One block per batch row.
// ---------------------------------------------------------------------------
__global__ __launch_bounds__(256) void fc_kernel(
    const float* __restrict__ W_fc, const float* __restrict__ b_fc,
    float* __restrict__ out)
{
    __shared__ float hsv[H_];
    const int b = blockIdx.x;
    const int tid = threadIdx.x;
    for (int k = tid; k < H_; k += 256) hsv[k] = g_h[0][(size_t)b * H_ + k];
    __syncthreads();

    const int o = tid;  // O_ == 256 == blockDim
    const float* __restrict__ wrow = W_fc + (size_t)o * H_;
    float acc = 0.f;
    #pragma unroll 8
    for (int k = 0; k < H_; k++) acc = fmaf(hsv[k], wrow[k], acc);
    out[(size_t)b * O_ + o] = acc + b_fc[o];
}

// Write hidden-state output (second tuple element) after the fc output.
__global__ void copy_hidden(float* __restrict__ dst)
{
    int idx = blockIdx.x * blockDim.x + threadIdx.x;
    if (idx < B_ * H_) dst[idx] = g_h[0][idx];
}

// ---------------------------------------------------------------------------
extern "C" void kernel_launch(void* const* d_in, const int* in_sizes, int n_in,
                              void* d_out, int out_size)
{
    const float* x      = (const float*)d_in[0];
    const float* hidden = (const float*)d_in[1];
    const float* W_ih   = (const float*)d_in[2];
    const float* W_hh   = (const float*)d_in[3];
    const float* b_ih   = (const float*)d_in[4];
    const float* b_hh   = (const float*)d_in[5];
    const float* W_fc   = (const float*)d_in[6];
    const float* b_fc   = (const float*)d_in[7];
    float* out = (float*)d_out;

    // 1) input projection for all timesteps (fully parallel)
    xp_gemm<<<dim3((B_ * T_) / 64, H_ / 64), 256>>>(x, W_ih, b_ih, b_hh);

    // 2) init hidden state
    init_h<<<(B_ * H_ + 255) / 256, 256>>>(hidden);

    // 3) sequential recurrence: 512 graph nodes
    for (int t = 0; t < T_; t++)
        step_gemm<<<dim3(B_ / 32, H_ / 32), 256>>>(W_hh, t);

    // 4) fc epilogue on h_last (in g_h[0] after even number of steps)
    fc_kernel<<<B_, 256>>>(W_fc, b_fc, out);

    // 5) second output: final hidden state [1,B,H], if the harness expects it
    if (out_size >= B_ * O_ + B_ * H_)
        copy_hidden<<<(B_ * H_ + 255) / 256, 256>>>(out + B_ * O_);
}

// round 8
// speedup vs baseline: 4.0759x; 4.0759x over previous
#include <cuda_runtime.h>
#include <cuda_bf16.h>
#include <math.h>
#include <stdint.h>

// Problem constants
#define B_ 128
#define T_ 512
#define I_ 256
#define H_ 1024
#define O_ 256

#define NB   128      // persistent grid: 4 M-tiles x 32 N-tiles
#define NTHR 128      // 4 warps per CTA

// ---------------------------------------------------------------------------
// Device-global scratch (allocation-free per harness rules)
// ---------------------------------------------------------------------------
__device__ __nv_bfloat16 g_x_hi[(size_t)B_ * T_ * I_];
__device__ __nv_bfloat16 g_x_lo[(size_t)B_ * T_ * I_];
__device__ __nv_bfloat16 g_h_hi[2][B_ * H_];
__device__ __nv_bfloat16 g_h_lo[2][B_ * H_];
__device__ __nv_bfloat16 g_Whh_hi[H_ * H_];
__device__ __nv_bfloat16 g_Whh_lo[H_ * H_];
__device__ __nv_bfloat16 g_Wih_hi[H_ * I_];
__device__ __nv_bfloat16 g_Wih_lo[H_ * I_];
__device__ float g_h32[B_ * H_];
__device__ unsigned g_bar_count;   // zero-init; restored to 0 by protocol
__device__ unsigned g_bar_phase;   // monotonic

// ---------------------------------------------------------------------------
// SMEM layout (dynamic)
// ---------------------------------------------------------------------------
#define SM_WHH_HI 0            // 32 rows x 2048B
#define SM_WHH_LO 65536
#define SM_WIH_HI 131072       // 32 rows x 512B
#define SM_WIH_LO 147456
#define SM_ASTAGE 163840       // 2 stages x 16384 (hi 8KB + lo 8KB each)
#define SM_BIAS   196608       // 32 floats
#define SM_TOTAL  196864

// ---------------------------------------------------------------------------
// PTX helpers (all portable ISA: valid for plain sm_103 target)
// ---------------------------------------------------------------------------
__device__ __forceinline__ uint32_t smem_u32(const void* p) {
    uint32_t a;
    asm("{ .reg .u64 t; cvta.to.shared.u64 t, %1; cvt.u32.u64 %0, t; }" : "=r"(a) : "l"(p));
    return a;
}

__device__ __forceinline__ void cp16(uint32_t saddr, const void* gptr) {
    asm volatile("cp.async.cg.shared.global [%0], [%1], 16;"
                 :: "r"(saddr), "l"(__cvta_generic_to_global(gptr)));
}

__device__ __forceinline__ void ldsm_x4(uint32_t* r, uint32_t addr) {
    asm volatile("ldmatrix.sync.aligned.m8n8.x4.shared.b16 {%0,%1,%2,%3}, [%4];"
                 : "=r"(r[0]), "=r"(r[1]), "=r"(r[2]), "=r"(r[3]) : "r"(addr));
}

__device__ __forceinline__ void mma16816(float* c, const uint32_t* a, uint32_t b0, uint32_t b1) {
    asm volatile(
        "mma.sync.aligned.m16n8k16.row.col.f32.bf16.bf16.f32 "
        "{%0,%1,%2,%3}, {%4,%5,%6,%7}, {%8,%9}, {%0,%1,%2,%3};"
        : "+f"(c[0]), "+f"(c[1]), "+f"(c[2]), "+f"(c[3])
        : "r"(a[0]), "r"(a[1]), "r"(a[2]), "r"(a[3]), "r"(b0), "r"(b1));
}

// Sense-reversing grid barrier (all NB CTAs co-resident by construction)
__device__ __forceinline__ void grid_barrier(unsigned* phase) {
    __syncthreads();
    if (threadIdx.x == 0) {
        unsigned target = *phase + 1;
        __threadfence();
        if (atomicAdd(&g_bar_count, 1) == NB - 1) {
            g_bar_count = 0;
            __threadfence();
            atomicExch(&g_bar_phase, target);
        } else {
            while (((volatile unsigned*)&g_bar_phase)[0] != target) {}
            __threadfence();
        }
        *phase = target;
    }
    __syncthreads();
}

// ---------------------------------------------------------------------------
// Split / init prep kernels
// ---------------------------------------------------------------------------
__global__ void split_pair(const float* __restrict__ src,
                           __nv_bfloat16* __restrict__ hi,
                           __nv_bfloat16* __restrict__ lo, int n)
{
    int i = blockIdx.x * blockDim.x + threadIdx.x;
    if (i < n) {
        float v = src[i];
        __nv_bfloat16 h = __float2bfloat16(v);
        hi[i] = h;
        lo[i] = __float2bfloat16(v - __bfloat162float(h));
    }
}

// ---------------------------------------------------------------------------
// A-stage chunk loaders (cp.async.cg -> L2-coherent across steps)
// Stage layout: hi 32x256B rows (swizzled), lo at +8192.
// ---------------------------------------------------------------------------
__device__ __forceinline__ void load_chunk_h(uint32_t sstage,
    const char* __restrict__ hhi, const char* __restrict__ hlo, int m0, int c, int tid)
{
    #pragma unroll
    for (int i = 0; i < 4; i++) {
        int u = tid + i * NTHR;
        int row = u >> 4, uk = u & 15;
        int so = row * 256 + ((uk * 16) ^ ((row & 7) * 16));
        size_t go = (size_t)(m0 + row) * 2048 + (size_t)c * 256 + uk * 16;
        cp16(sstage + so, hhi + go);
        cp16(sstage + 8192 + so, hlo + go);
    }
}

__device__ __forceinline__ void load_chunk_x(uint32_t sstage, int m0, int cx, int t, int tid)
{
    #pragma unroll
    for (int i = 0; i < 4; i++) {
        int u = tid + i * NTHR;
        int row = u >> 4, uk = u & 15;
        int so = row * 256 + ((uk * 16) ^ ((row & 7) * 16));
        size_t go = ((size_t)(m0 + row) * T_ + t) * 512 + (size_t)cx * 256 + uk * 16;
        cp16(sstage + so, (const char*)g_x_hi + go);
        cp16(sstage + 8192 + so, (const char*)g_x_lo + go);
    }
}

// ---------------------------------------------------------------------------
// Persistent recurrence kernel: 512 steps, one launch.
// CTA (ctaM, ctaN): M-tile 32 batches, N-tile 32 hidden cols, K = 1024(h)+256(x).
// 4 warps, warp tile M16xN16, split-bf16 3-term mma, 2-parity accumulators.
// ---------------------------------------------------------------------------
__global__ __launch_bounds__(NTHR, 1) void rnn_persistent(
    const float* __restrict__ b_ih, const float* __restrict__ b_hh)
{
    extern __shared__ char sm[];
    const uint32_t smb = smem_u32(sm);
    const int tid = threadIdx.x;
    const int lid = tid & 31;
    const int wid = tid >> 5;
    const int wm = wid >> 1, wn = wid & 1;
    const int ctaM = blockIdx.x >> 5;
    const int ctaN = blockIdx.x & 31;
    const int m0 = ctaM * 32;
    const int n0 = ctaN * 32;

    // ---- Load persistent W slices into swizzled smem ----
    {
        const char* whh_hi = (const char*)g_Whh_hi;
        const char* whh_lo = (const char*)g_Whh_lo;
        for (int u = tid; u < 4096; u += NTHR) {
            int row = u >> 7, uk = u & 127;
            int so = row * 2048 + ((uk * 16) ^ ((row & 7) * 16));
            size_t go = (size_t)(n0 + row) * 2048 + (size_t)uk * 16;
            *(uint4*)(sm + SM_WHH_HI + so) = *(const uint4*)(whh_hi + go);
            *(uint4*)(sm + SM_WHH_LO + so) = *(const uint4*)(whh_lo + go);
        }
        // W_ih slice: 32 rows x 512 B = 1024 16-byte units
        const char* wih_hi = (const char*)g_Wih_hi;
        const char* wih_lo = (const char*)g_Wih_lo;
        for (int u = tid; u < 1024; u += NTHR) {
            int row = u >> 5, uk = u & 31;
            int so = row * 512 + ((uk * 16) ^ ((row & 7) * 16));
            size_t go = (size_t)(n0 + row) * 512 + (size_t)uk * 16;
            *(uint4*)(sm + SM_WIH_HI + so) = *(const uint4*)(wih_hi + go);
            *(uint4*)(sm + SM_WIH_LO + so) = *(const uint4*)(wih_lo + go);
        }
        if (tid < 32)
            ((float*)(sm + SM_BIAS))[tid] = b_ih[n0 + tid] + b_hh[n0 + tid];
    }

    unsigned phase = 0;
    if (tid == 0) phase = ((volatile unsigned*)&g_bar_phase)[0];
    __syncthreads();

    // Per-lane fragment address constants
    const int arow = (lid & 7) + ((lid >> 3) & 1) * 8;   // A row within warp M16
    const int aka2 = ((lid >> 4) & 1) * 16;              // A k-half byte offset
    const int axor = (arow & 7) * 16;
    const uint32_t a_lane = smb + SM_ASTAGE + (uint32_t)(wm * 16 + arow) * 256;

    const int brow = wn * 16 + (lid & 7) + ((lid >> 4) & 1) * 8;  // B (W) row
    const int bka2 = ((lid >> 3) & 1) * 16;
    const int bxor = (brow & 7) * 16;
    const uint32_t bhh_lane = smb + SM_WHH_HI + (uint32_t)brow * 2048;
    const uint32_t bih_lane = smb + SM_WIH_HI + (uint32_t)brow * 512;

    const int g  = lid >> 2;
    const int tg = lid & 3;

    for (int t = 0; t < T_; t++) {
        const char* hhi = (const char*)g_h_hi[t & 1];
        const char* hlo = (const char*)g_h_lo[t & 1];

        float acc[2][2][4];
        #pragma unroll
        for (int p = 0; p < 2; p++)
            #pragma unroll
            for (int n = 0; n < 2; n++)
                #pragma unroll
                for (int j = 0; j < 4; j++) acc[p][n][j] = 0.f;

        // K pipeline: chunks 0..7 = h (K=1024), chunks 8..9 = x_t (K=256)
        load_chunk_h(smb + SM_ASTAGE, hhi, hlo, m0, 0, tid);
        asm volatile("cp.async.commit_group;");

        for (int c = 0; c < 10; c++) {
            if (c + 1 < 10) {
                uint32_t st = smb + SM_ASTAGE + (uint32_t)((c + 1) & 1) * 16384;
                if (c + 1 < 8) load_chunk_h(st, hhi, hlo, m0, c + 1, tid);
                else           load_chunk_x(st, m0, c + 1 - 8, t, tid);
                asm volatile("cp.async.commit_group;");
                asm volatile("cp.async.wait_group 1;");
            } else {
                asm volatile("cp.async.wait_group 0;");
            }
            __syncthreads();

            const uint32_t a_base = a_lane + (uint32_t)(c & 1) * 16384;
            uint32_t b_base;   // hi-matrix lane base for this chunk
            uint32_t b_dlo;    // offset from hi to lo matrix
            int kb0;           // chunk byte offset within W row
            if (c < 8) { b_base = bhh_lane; b_dlo = 65536; kb0 = c * 256; }
            else       { b_base = bih_lane; b_dlo = 16384; kb0 = (c - 8) * 256; }

            #pragma unroll
            for (int kk = 0; kk < 8; kk++) {
                uint32_t ahi[4], alo[4], bh[4], bl[4];
                uint32_t ao = (uint32_t)((kk * 32 + aka2) ^ axor);
                ldsm_x4(ahi, a_base + ao);
                ldsm_x4(alo, a_base + 8192 + ao);
                uint32_t bo = (uint32_t)((kb0 + kk * 32 + bka2) ^ bxor);
                // B tile is [n][k] row-major; mma B fragment wants consecutive-k
                // pairs at fixed n -> NON-trans ldmatrix (R6 bug was .trans here).
                ldsm_x4(bh, b_base + bo);
                ldsm_x4(bl, b_base + b_dlo + bo);

                float* C0 = acc[kk & 1][0];
                float* C1 = acc[kk & 1][1];
                mma16816(C0, ahi, bh[0], bh[1]);   // Ahi*Bhi
                mma16816(C1, ahi, bh[2], bh[3]);
                mma16816(C0, ahi, bl[0], bl[1]);   // Ahi*Blo
                mma16816(C1, ahi, bl[2], bl[3]);
                mma16816(C0, alo, bh[0], bh[1]);   // Alo*Bhi
                mma16816(C1, alo, bh[2], bh[3]);
            }
            __syncthreads();
        }

        // Epilogue: +bias, tanh, split-bf16 store of h_{t+1}
        {
            __nv_bfloat16* __restrict__ ohi = g_h_hi[(t + 1) & 1];
            __nv_bfloat16* __restrict__ olo = g_h_lo[(t + 1) & 1];
            const float* bias = (const float*)(sm + SM_BIAS);
            const bool last = (t == T_ - 1);
            #pragma unroll
            for (int nt = 0; nt < 2; nt++) {
                int nloc = wn * 16 + nt * 8 + tg * 2;
                int ng = n0 + nloc;
                float b0v = bias[nloc], b1v = bias[nloc + 1];
                #pragma unroll
                for (int rp = 0; rp < 2; rp++) {
                    int mg = m0 + wm * 16 + g + rp * 8;
                    float v0 = tanhf(acc[0][nt][rp * 2 + 0] + acc[1][nt][rp * 2 + 0] + b0v);
                    float v1 = tanhf(acc[0][nt][rp * 2 + 1] + acc[1][nt][rp * 2 + 1] + b1v);
                    __nv_bfloat16 h0 = __float2bfloat16(v0);
                    __nv_bfloat16 h1 = __float2bfloat16(v1);
                    __nv_bfloat16 l0 = __float2bfloat16(v0 - __bfloat162float(h0));
                    __nv_bfloat16 l1 = __float2bfloat16(v1 - __bfloat162float(h1));
                    size_t idx = (size_t)mg * H_ + ng;
                    *(uint32_t*)(ohi + idx) =
                        ((uint32_t)*(uint16_t*)&h1 << 16) | *(uint16_t*)&h0;
                    *(uint32_t*)(olo + idx) =
                        ((uint32_t)*(uint16_t*)&l1 << 16) | *(uint16_t*)&l0;
                    if (last) {
                        float2 f2v; f2v.x = v0; f2v.y = v1;
                        *(float2*)(g_h32 + idx) = f2v;
                    }
                }
            }
        }

        grid_barrier(&phase);
    }
}

// ---------------------------------------------------------------------------
// fc epilogue on final hidden state
// ---------------------------------------------------------------------------
__global__ __launch_bounds__(256) void fc_kernel(
    const float* __restrict__ W_fc, const float* __restrict__ b_fc,
    float* __restrict__ out)
{
    __shared__ float hsv[H_];
    const int b = blockIdx.x;
    const int tid = threadIdx.x;
    for (int k = tid; k < H_; k += 256) hsv[k] = g_h32[(size_t)b * H_ + k];
    __syncthreads();

    const int o = tid;
    const float* __restrict__ wrow = W_fc + (size_t)o * H_;
    float acc = 0.f;
    #pragma unroll 8
    for (int k = 0; k < H_; k++) acc = fmaf(hsv[k], wrow[k], acc);
    out[(size_t)b * O_ + o] = acc + b_fc[o];
}

__global__ void copy_hidden(float* __restrict__ dst)
{
    int idx = blockIdx.x * blockDim.x + threadIdx.x;
    if (idx < B_ * H_) dst[idx] = g_h32[idx];
}

// ---------------------------------------------------------------------------
extern "C" void kernel_launch(void* const* d_in, const int* in_sizes, int n_in,
                              void* d_out, int out_size)
{
    const float* x      = (const float*)d_in[0];
    const float* hidden = (const float*)d_in[1];
    const float* W_ih   = (const float*)d_in[2];
    const float* W_hh   = (const float*)d_in[3];
    const float* b_ih   = (const float*)d_in[4];
    const float* b_hh   = (const float*)d_in[5];
    const float* W_fc   = (const float*)d_in[6];
    const float* b_fc   = (const float*)d_in[7];
    float* out = (float*)d_out;

    cudaFuncSetAttribute(rnn_persistent, cudaFuncAttributeMaxDynamicSharedMemorySize,
                         SM_TOTAL);

    // Resolve device-global scratch addresses (host-side, not a stream op)
    static __nv_bfloat16 *p_xhi = nullptr, *p_xlo = nullptr, *p_whhhi = nullptr,
                         *p_whhlo = nullptr, *p_wihhi = nullptr, *p_wihlo = nullptr,
                         *p_hhi = nullptr, *p_hlo = nullptr;
    if (!p_xhi) {
        cudaGetSymbolAddress((void**)&p_xhi,   g_x_hi);
        cudaGetSymbolAddress((void**)&p_xlo,   g_x_lo);
        cudaGetSymbolAddress((void**)&p_whhhi, g_Whh_hi);
        cudaGetSymbolAddress((void**)&p_whhlo, g_Whh_lo);
        cudaGetSymbolAddress((void**)&p_wihhi, g_Wih_hi);
        cudaGetSymbolAddress((void**)&p_wihlo, g_Wih_lo);
        cudaGetSymbolAddress((void**)&p_hhi,   g_h_hi);
        cudaGetSymbolAddress((void**)&p_hlo,   g_h_lo);
    }

    // 1) split inputs to bf16 hi/lo
    split_pair<<<(B_ * T_ * I_ + 255) / 256, 256>>>(x, p_xhi, p_xlo, B_ * T_ * I_);
    split_pair<<<(H_ * H_ + 255) / 256, 256>>>(W_hh, p_whhhi, p_whhlo, H_ * H_);
    split_pair<<<(H_ * I_ + 255) / 256, 256>>>(W_ih, p_wihhi, p_wihlo, H_ * I_);
    split_pair<<<(B_ * H_ + 255) / 256, 256>>>(hidden, p_hhi, p_hlo, B_ * H_);

    // 2) full recurrence in ONE persistent launch
    rnn_persistent<<<NB, NTHR, SM_TOTAL>>>(b_ih, b_hh);

    // 3) fc epilogue + hidden output
    fc_kernel<<<B_, 256>>>(W_fc, b_fc, out);
    if (out_size >= B_ * O_ + B_ * H_)
        copy_hidden<<<(B_ * H_ + 255) / 256, 256>>>(out + B_ * O_);
}